// round 13
// baseline (speedup 1.0000x reference)
#include <cuda_runtime.h>
#include <mma.h>
#include <math.h>
#include <stdint.h>

using namespace nvcuda;

#define N_NODES 10000
#define DIM     1024
#define NREL    8
#define NEDGE   80000
#define K1      9216
#define K2      2048

#define BM 128
#define BN 128
#define BK 32
#define NTHREADS 256
#define NSTAGE 3
#define ALD 36                          /* A smem row stride (floats) */
#define BLD 132                         /* B smem row stride (floats) */
#define CLD 132                         /* epilogue staging stride    */
#define A_TILE_FLOATS (BM * ALD)        /* 4608 */
#define B_TILE_FLOATS (BK * BLD)        /* 4224 */
#define STAGE_FLOATS  (A_TILE_FLOATS + B_TILE_FLOATS)   /* 8832   */
#define SMEM_BYTES    (NSTAGE * STAGE_FLOATS * 4)       /* 105984 */

/* Scratch device globals — PROVEN set only (extra large statics
   correlate 3/3 with the 0.9113 wrong-answer signature).          */
__device__ float g_agg[(size_t)N_NODES * NREL * DIM];
__device__ float g_cnt[N_NODES * NREL];
__device__ float g_U[(size_t)N_NODES * DIM];
__device__ int   g_is64;

__device__ __forceinline__ float f2tf32(float f) {
    uint32_t r;
    asm("cvt.rna.tf32.f32 %0, %1;" : "=r"(r) : "f"(f));
    return __uint_as_float(r);
}
#define BAR_SYNC(id)   asm volatile("bar.sync %0, 256;"   :: "r"(id) : "memory")
#define BAR_ARRIVE(id) asm volatile("bar.arrive %0, 256;" :: "r"(id) : "memory")

/* ================= prep kernels (verbatim, proven) ================= */
__global__ void detect_kernel(const int* __restrict__ ei) {
    if (threadIdx.x == 0 && blockIdx.x == 0) {
        int allzero = 1;
        for (int i = 1; i < 4096; i += 2)
            if (ei[i] != 0) { allzero = 0; break; }
        g_is64 = allzero;
    }
}

__global__ void zero_scratch_kernel() {
    size_t idx    = (size_t)blockIdx.x * blockDim.x + threadIdx.x;
    size_t stride = (size_t)gridDim.x * blockDim.x;
    float4* agg4 = reinterpret_cast<float4*>(g_agg);
    const size_t nagg4 = (size_t)N_NODES * NREL * DIM / 4;
    for (size_t i = idx; i < nagg4; i += stride)
        agg4[i] = make_float4(0.f, 0.f, 0.f, 0.f);
    float4* cnt4 = reinterpret_cast<float4*>(g_cnt);
    const size_t ncnt4 = (size_t)N_NODES * NREL / 4;
    for (size_t i = idx; i < ncnt4; i += stride)
        cnt4[i] = make_float4(0.f, 0.f, 0.f, 0.f);
}

__global__ __launch_bounds__(256)
void scatter_kernel(const float* __restrict__ x,
                    const void* __restrict__ edge_index,
                    const void* __restrict__ edge_type) {
    int e = blockIdx.x;
    int src, dst, r;
    if (g_is64) {
        const long long* ei = (const long long*)edge_index;
        const long long* et = (const long long*)edge_type;
        src = (int)ei[e]; dst = (int)ei[NEDGE + e]; r = (int)et[e];
    } else {
        const int* ei = (const int*)edge_index;
        const int* et = (const int*)edge_type;
        src = ei[e]; dst = ei[NEDGE + e]; r = et[e];
    }
    const float4* xs = reinterpret_cast<const float4*>(x + (size_t)src * DIM);
    float* out = g_agg + ((size_t)dst * NREL + r) * DIM;
    int t = threadIdx.x;
    float4 v = xs[t];
    atomicAdd(out + t * 4 + 0, v.x);
    atomicAdd(out + t * 4 + 1, v.y);
    atomicAdd(out + t * 4 + 2, v.z);
    atomicAdd(out + t * 4 + 3, v.w);
    if (t == 0)
        atomicAdd(&g_cnt[dst * NREL + r], 1.0f);
}

/* ================= warp-specialized WMMA tf32 GEMM =================
   Warps 0-3: producers (LDG -> tf32 cvt / mean-normalize -> STS) into
   a 3-stage smem ring. Warps 4-7: consumers, 64x64 WMMA tile each.
   Handoff via named barriers (full: ids 1-3, empty: ids 4-6), both
   groups participate in every barrier (128 arrive + 128 sync = 256).
   Occupancy 1 -> 255-reg budget -> no spills.
   MODE 0: U = [x | mean] @ [root ; weight] + bias     (K = 9216)
   MODE 1: z = [u | x] @ w_gate + b_gate; fused gate   (K = 2048)      */
template <int MODE>
__global__ __launch_bounds__(NTHREADS, 1)
void gemm_ws(const float* __restrict__ x,
             const float* __restrict__ B0,      /* root   | w_gate */
             const float* __restrict__ B1,      /* weight | unused */
             const float* __restrict__ bvec,
             float* __restrict__ out) {
    extern __shared__ float smem[];
    const int tid = threadIdx.x;
    const int wid = tid >> 5;
    const int m0  = blockIdx.y * BM;
    const int n0  = blockIdx.x * BN;
    const int KDIM = MODE ? K2 : K1;
    const int NC   = KDIM / BK;

    if (wid < 4) {
        /* ---------------- producers ---------------- */
        const int ptid = tid;              /* 0..127 */
        for (int ci = 0; ci < NC; ci++) {
            const int s  = ci % NSTAGE;
            const int k0 = ci * BK;
            if (ci >= NSTAGE) BAR_SYNC(4 + s);        /* wait stage empty */
            float* Abuf = smem + s * STAGE_FLOATS;
            float* Bbuf = Abuf + A_TILE_FLOATS;
            /* A tile: 128 rows x 32 cols = 1024 float4, 8 per thread */
#pragma unroll
            for (int t = 0; t < 8; t++) {
                int idx = ptid + t * 128;
                int row = idx >> 3;
                int c4  = (idx & 7) << 2;
                int grow = m0 + row;
                float4 v = make_float4(0.f, 0.f, 0.f, 0.f);
                if (grow < N_NODES) {
                    int k = k0 + c4;
                    if (MODE == 0) {
                        if (k < DIM) {
                            v = *reinterpret_cast<const float4*>(
                                x + (size_t)grow * DIM + k);
                        } else {
                            int kk = k - DIM;
                            int r  = kk >> 10;
                            float sc = 1.0f / fmaxf(g_cnt[grow * NREL + r], 1.0f);
                            float4 a = *reinterpret_cast<const float4*>(
                                g_agg + (size_t)grow * (NREL * DIM) + kk);
                            v.x = a.x * sc; v.y = a.y * sc;
                            v.z = a.z * sc; v.w = a.w * sc;
                        }
                    } else {
                        const float* Ap = (k < DIM)
                            ? (g_U + (size_t)grow * DIM + k)
                            : (x + (size_t)grow * DIM + (k - DIM));
                        v = *reinterpret_cast<const float4*>(Ap);
                    }
                }
                float* p = Abuf + row * ALD + c4;
                p[0] = f2tf32(v.x); p[1] = f2tf32(v.y);
                p[2] = f2tf32(v.z); p[3] = f2tf32(v.w);
            }
            /* B tile: 32 rows x 128 cols = 1024 float4, 8 per thread */
#pragma unroll
            for (int t = 0; t < 8; t++) {
                int idx = ptid + t * 128;
                int kr  = idx >> 5;
                int c4  = (idx & 31) << 2;
                int k   = k0 + kr;
                const float* src;
                if (MODE == 0)
                    src = (k < DIM) ? (B0 + (size_t)k * DIM + n0 + c4)
                                    : (B1 + (size_t)(k - DIM) * DIM + n0 + c4);
                else
                    src = B0 + (size_t)k * DIM + n0 + c4;
                float4 v = *reinterpret_cast<const float4*>(src);
                float* p = Bbuf + kr * BLD + c4;
                p[0] = f2tf32(v.x); p[1] = f2tf32(v.y);
                p[2] = f2tf32(v.z); p[3] = f2tf32(v.w);
            }
            BAR_ARRIVE(1 + s);                        /* stage full */
        }
        /* join epilogue */
        __syncthreads();   /* consumers staging accumulators */
        __syncthreads();
    } else {
        /* ---------------- consumers ---------------- */
        const int cw = wid - 4;
        const int wm = (cw & 1) * 64;
        const int wn = (cw >> 1) * 64;

        wmma::fragment<wmma::accumulator, 16, 16, 8, float> acc[4][4];
#pragma unroll
        for (int mt = 0; mt < 4; mt++)
#pragma unroll
            for (int nt = 0; nt < 4; nt++)
                wmma::fill_fragment(acc[mt][nt], 0.0f);

        for (int ci = 0; ci < NC; ci++) {
            const int s = ci % NSTAGE;
            BAR_SYNC(1 + s);                          /* wait stage full */
            const float* Abuf = smem + s * STAGE_FLOATS;
            const float* Bbuf = Abuf + A_TILE_FLOATS;
#pragma unroll
            for (int kk = 0; kk < 4; kk++) {
                wmma::fragment<wmma::matrix_b, 16, 16, 8,
                               wmma::precision::tf32, wmma::row_major> fb[4];
#pragma unroll
                for (int nt = 0; nt < 4; nt++)
                    wmma::load_matrix_sync(fb[nt],
                        Bbuf + (kk * 8) * BLD + wn + nt * 16, BLD);
#pragma unroll
                for (int mt = 0; mt < 4; mt++) {
                    wmma::fragment<wmma::matrix_a, 16, 16, 8,
                                   wmma::precision::tf32, wmma::row_major> fa;
                    wmma::load_matrix_sync(fa,
                        Abuf + (wm + mt * 16) * ALD + kk * 8, ALD);
#pragma unroll
                    for (int nt = 0; nt < 4; nt++)
                        wmma::mma_sync(acc[mt][nt], fa, fb[nt], acc[mt][nt]);
                }
            }
            BAR_ARRIVE(4 + s);                        /* stage empty */
        }

        /* stage accumulators into smem */
        __syncthreads();
        float* stg = smem;
#pragma unroll
        for (int mt = 0; mt < 4; mt++)
#pragma unroll
            for (int nt = 0; nt < 4; nt++)
                wmma::store_matrix_sync(stg + (wm + mt * 16) * CLD + wn + nt * 16,
                                        acc[mt][nt], CLD, wmma::mem_row_major);
        __syncthreads();
    }

    /* ---- all 256 threads: elementwise epilogue from staging ---- */
    const float* stg = smem;
#pragma unroll
    for (int t = 0; t < 16; t++) {
        int idx = tid + t * NTHREADS;        /* 4096 float4 = 128x128 */
        int row = idx >> 5;
        int c4  = (idx & 31) << 2;
        int grow = m0 + row;
        if (grow >= N_NODES) continue;
        int gc = n0 + c4;
        const float* sp = stg + row * CLD + c4;
        float4 bv = *reinterpret_cast<const float4*>(bvec + gc);
        float z0 = sp[0] + bv.x, z1 = sp[1] + bv.y;
        float z2 = sp[2] + bv.z, z3 = sp[3] + bv.w;
        size_t o = (size_t)grow * DIM + gc;
        if (MODE == 0) {
            *reinterpret_cast<float4*>(g_U + o) = make_float4(z0, z1, z2, z3);
        } else {
            float4 u4 = *reinterpret_cast<const float4*>(g_U + o);
            float4 x4 = *reinterpret_cast<const float4*>(x + o);
            float h0 = tanhf(u4.x) * z0 + x4.x * (1.0f - z0);
            float h1 = tanhf(u4.y) * z1 + x4.y * (1.0f - z1);
            float h2 = tanhf(u4.z) * z2 + x4.z * (1.0f - z2);
            float h3 = tanhf(u4.w) * z3 + x4.w * (1.0f - z3);
            *reinterpret_cast<float4*>(out + o) = make_float4(h0, h1, h2, h3);
        }
    }
}

/* ================= launch ================= */
extern "C" void kernel_launch(void* const* d_in, const int* in_sizes, int n_in,
                              void* d_out, int out_size) {
    const float* x      = (const float*)d_in[0];
    const void*  ei     = d_in[1];
    const void*  et     = d_in[2];
    const float* weight = (const float*)d_in[3];
    const float* root   = (const float*)d_in[4];
    const float* bias   = (const float*)d_in[5];
    const float* w_gate = (const float*)d_in[6];
    const float* b_gate = (const float*)d_in[7];
    float*       out    = (float*)d_out;

    cudaFuncSetAttribute(gemm_ws<0>, cudaFuncAttributeMaxDynamicSharedMemorySize, SMEM_BYTES);
    cudaFuncSetAttribute(gemm_ws<1>, cudaFuncAttributeMaxDynamicSharedMemorySize, SMEM_BYTES);

    detect_kernel<<<1, 32>>>((const int*)ei);
    zero_scratch_kernel<<<1024, 256>>>();
    scatter_kernel<<<NEDGE, 256>>>(x, ei, et);

    dim3 grid(DIM / BN, (N_NODES + BM - 1) / BM);   /* 8 x 79 */
    gemm_ws<0><<<grid, NTHREADS, SMEM_BYTES>>>(x, root, weight, bias, nullptr);
    gemm_ws<1><<<grid, NTHREADS, SMEM_BYTES>>>(x, w_gate, nullptr, b_gate, out);
}

// round 14
// speedup vs baseline: 1.5459x; 1.5459x over previous
#include <cuda_runtime.h>
#include <mma.h>
#include <math.h>
#include <stdint.h>

using namespace nvcuda;

#define N_NODES 10000
#define DIM     1024
#define NREL    8
#define NEDGE   80000
#define K1      9216
#define K2      2048

#define BM 128
#define BN 256
#define BK 32
#define NTHREADS 512
#define ALD 36                          /* A smem row stride (floats) */
#define BLD 260                         /* B smem row stride (floats) */
#define CLD 260                         /* epilogue staging stride    */
#define A_TILE_FLOATS (BM * ALD)        /* 4608  */
#define B_TILE_FLOATS (BK * BLD)        /* 8320  */
#define STAGE_FLOATS  (A_TILE_FLOATS + B_TILE_FLOATS)   /* 12928 */
#define SMEM_BYTES    (BM * CLD * 4)    /* 133120 >= 2*STAGE_FLOATS*4 (103424) */

/* Scratch device globals — PROVEN set only. */
__device__ float g_agg[(size_t)N_NODES * NREL * DIM];
__device__ float g_cnt[N_NODES * NREL];
__device__ float g_U[(size_t)N_NODES * DIM];
__device__ int   g_is64;

__device__ __forceinline__ float f2tf32(float f) {
    uint32_t r;
    asm("cvt.rna.tf32.f32 %0, %1;" : "=r"(r) : "f"(f));
    return __uint_as_float(r);
}

/* ================= prep kernels (verbatim, proven) ================= */
__global__ void detect_kernel(const int* __restrict__ ei) {
    if (threadIdx.x == 0 && blockIdx.x == 0) {
        int allzero = 1;
        for (int i = 1; i < 4096; i += 2)
            if (ei[i] != 0) { allzero = 0; break; }
        g_is64 = allzero;
    }
}

__global__ void zero_scratch_kernel() {
    size_t idx    = (size_t)blockIdx.x * blockDim.x + threadIdx.x;
    size_t stride = (size_t)gridDim.x * blockDim.x;
    float4* agg4 = reinterpret_cast<float4*>(g_agg);
    const size_t nagg4 = (size_t)N_NODES * NREL * DIM / 4;
    for (size_t i = idx; i < nagg4; i += stride)
        agg4[i] = make_float4(0.f, 0.f, 0.f, 0.f);
    float4* cnt4 = reinterpret_cast<float4*>(g_cnt);
    const size_t ncnt4 = (size_t)N_NODES * NREL / 4;
    for (size_t i = idx; i < ncnt4; i += stride)
        cnt4[i] = make_float4(0.f, 0.f, 0.f, 0.f);
}

__global__ __launch_bounds__(256)
void scatter_kernel(const float* __restrict__ x,
                    const void* __restrict__ edge_index,
                    const void* __restrict__ edge_type) {
    int e = blockIdx.x;
    int src, dst, r;
    if (g_is64) {
        const long long* ei = (const long long*)edge_index;
        const long long* et = (const long long*)edge_type;
        src = (int)ei[e]; dst = (int)ei[NEDGE + e]; r = (int)et[e];
    } else {
        const int* ei = (const int*)edge_index;
        const int* et = (const int*)edge_type;
        src = ei[e]; dst = ei[NEDGE + e]; r = et[e];
    }
    const float4* xs = reinterpret_cast<const float4*>(x + (size_t)src * DIM);
    float* out = g_agg + ((size_t)dst * NREL + r) * DIM;
    int t = threadIdx.x;
    float4 v = xs[t];
    atomicAdd(out + t * 4 + 0, v.x);
    atomicAdd(out + t * 4 + 1, v.y);
    atomicAdd(out + t * 4 + 2, v.z);
    atomicAdd(out + t * 4 + 3, v.w);
    if (t == 0)
        atomicAdd(&g_cnt[dst * NREL + r], 1.0f);
}

/* ================= WMMA tf32 GEMM, 512 threads / 16 warps ==========
   One CTA per SM; warp tile 64x32 (acc = 64 regs) so the R7-proven
   register-prefetch double-buffer pipeline fits the 128-reg budget
   without spilling. Rounding + mean-normalization fused at STS.
   MODE 0: U = [x | mean] @ [root ; weight] + bias     (K = 9216)
   MODE 1: z = [u | x] @ w_gate + b_gate; fused gate   (K = 2048)      */
template <int MODE>
__global__ __launch_bounds__(NTHREADS, 1)
void gemm_wmma(const float* __restrict__ x,
               const float* __restrict__ B0,      /* root   | w_gate  */
               const float* __restrict__ B1,      /* weight | unused  */
               const float* __restrict__ bvec,
               float* __restrict__ out) {
    extern __shared__ float smem[];
    const int tid = threadIdx.x;
    const int wid = tid >> 5;
    const int m0  = blockIdx.y * BM;
    const int n0  = blockIdx.x * BN;
    const int KDIM = MODE ? K2 : K1;
    const int NC   = KDIM / BK;

    float* Abuf[2] = { smem,                 smem + STAGE_FLOATS };
    float* Bbuf[2] = { smem + A_TILE_FLOATS, smem + STAGE_FLOATS + A_TILE_FLOATS };

    const int wm = (wid & 1) * 64;      /* warp rows: 4 x 16 */
    const int wn = (wid >> 1) * 32;     /* warp cols: 2 x 16 */

    wmma::fragment<wmma::accumulator, 16, 16, 8, float> acc[4][2];
#pragma unroll
    for (int mt = 0; mt < 4; mt++)
#pragma unroll
        for (int nt = 0; nt < 2; nt++)
            wmma::fill_fragment(acc[mt][nt], 0.0f);

    float4 ra[2], rb[4];

    /* global -> registers (prefetch): A 128x32, B 32x256 */
    auto ldg_tile = [&](int ci) {
        const int k0 = ci * BK;
#pragma unroll
        for (int t = 0; t < 2; t++) {
            int idx = tid + t * NTHREADS;
            int row = idx >> 3;                  /* 8 float4 per A row */
            int c4  = (idx & 7) << 2;
            int grow = m0 + row;
            float4 v = make_float4(0.f, 0.f, 0.f, 0.f);
            if (grow < N_NODES) {
                int k = k0 + c4;
                if (MODE == 0) {
                    if (k < DIM) {
                        v = *reinterpret_cast<const float4*>(x + (size_t)grow * DIM + k);
                    } else {
                        int kk = k - DIM;
                        int r  = kk >> 10;
                        float s = 1.0f / fmaxf(g_cnt[grow * NREL + r], 1.0f);
                        float4 a = *reinterpret_cast<const float4*>(
                            g_agg + (size_t)grow * (NREL * DIM) + kk);
                        v.x = a.x * s; v.y = a.y * s; v.z = a.z * s; v.w = a.w * s;
                    }
                } else {
                    const float* Ap = (k < DIM)
                        ? (g_U + (size_t)grow * DIM + k)
                        : (x + (size_t)grow * DIM + (k - DIM));
                    v = *reinterpret_cast<const float4*>(Ap);
                }
            }
            ra[t] = v;
        }
#pragma unroll
        for (int t = 0; t < 4; t++) {
            int idx = tid + t * NTHREADS;
            int kr  = idx >> 6;                  /* 64 float4 per B row */
            int c4  = (idx & 63) << 2;
            int k   = k0 + kr;
            const float* src;
            if (MODE == 0)
                src = (k < DIM) ? (B0 + (size_t)k * DIM + n0 + c4)
                                : (B1 + (size_t)(k - DIM) * DIM + n0 + c4);
            else
                src = B0 + (size_t)k * DIM + n0 + c4;
            rb[t] = *reinterpret_cast<const float4*>(src);
        }
    };

    /* registers -> smem with tf32 rounding */
    auto st_tile = [&](int s) {
#pragma unroll
        for (int t = 0; t < 2; t++) {
            int idx = tid + t * NTHREADS;
            int row = idx >> 3;
            int c4  = (idx & 7) << 2;
            float* p = Abuf[s] + row * ALD + c4;
            p[0] = f2tf32(ra[t].x); p[1] = f2tf32(ra[t].y);
            p[2] = f2tf32(ra[t].z); p[3] = f2tf32(ra[t].w);
        }
#pragma unroll
        for (int t = 0; t < 4; t++) {
            int idx = tid + t * NTHREADS;
            int kr  = idx >> 6;
            int c4  = (idx & 63) << 2;
            float* p = Bbuf[s] + kr * BLD + c4;
            p[0] = f2tf32(rb[t].x); p[1] = f2tf32(rb[t].y);
            p[2] = f2tf32(rb[t].z); p[3] = f2tf32(rb[t].w);
        }
    };

    ldg_tile(0);

    for (int ci = 0; ci < NC; ci++) {
        const int s = ci & 1;
        st_tile(s);
        __syncthreads();
        if (ci + 1 < NC) ldg_tile(ci + 1);   /* LDGs retire under MMA */

#pragma unroll
        for (int kk = 0; kk < 4; kk++) {
            wmma::fragment<wmma::matrix_b, 16, 16, 8,
                           wmma::precision::tf32, wmma::row_major> fb[2];
#pragma unroll
            for (int nt = 0; nt < 2; nt++)
                wmma::load_matrix_sync(fb[nt], Bbuf[s] + (kk * 8) * BLD + wn + nt * 16, BLD);
#pragma unroll
            for (int mt = 0; mt < 4; mt++) {
                wmma::fragment<wmma::matrix_a, 16, 16, 8,
                               wmma::precision::tf32, wmma::row_major> fa;
                wmma::load_matrix_sync(fa, Abuf[s] + (wm + mt * 16) * ALD + kk * 8, ALD);
#pragma unroll
                for (int nt = 0; nt < 2; nt++)
                    wmma::mma_sync(acc[mt][nt], fa, fb[nt], acc[mt][nt]);
            }
        }
        /* single sync/iter: sync at iter ci+1 fences ci's readers of
           buffer s from ci+2's writers of s (proven R7/R11/R12). */
    }

    /* ---- epilogue: stage accumulators in smem, then elementwise ---- */
    __syncthreads();
    float* stg = smem;                       /* 128 x CLD */
#pragma unroll
    for (int mt = 0; mt < 4; mt++)
#pragma unroll
        for (int nt = 0; nt < 2; nt++)
            wmma::store_matrix_sync(stg + (wm + mt * 16) * CLD + wn + nt * 16,
                                    acc[mt][nt], CLD, wmma::mem_row_major);
    __syncthreads();

#pragma unroll
    for (int t = 0; t < 16; t++) {
        int idx = tid + t * NTHREADS;        /* 8192 float4 = 128x256 */
        int row = idx >> 6;
        int c4  = (idx & 63) << 2;
        int grow = m0 + row;
        if (grow >= N_NODES) continue;
        int gc = n0 + c4;
        const float* sp = stg + row * CLD + c4;
        float4 bv = *reinterpret_cast<const float4*>(bvec + gc);
        float z0 = sp[0] + bv.x, z1 = sp[1] + bv.y;
        float z2 = sp[2] + bv.z, z3 = sp[3] + bv.w;
        size_t o = (size_t)grow * DIM + gc;
        if (MODE == 0) {
            *reinterpret_cast<float4*>(g_U + o) = make_float4(z0, z1, z2, z3);
        } else {
            float4 u4 = *reinterpret_cast<const float4*>(g_U + o);
            float4 x4 = *reinterpret_cast<const float4*>(x + o);
            float h0 = tanhf(u4.x) * z0 + x4.x * (1.0f - z0);
            float h1 = tanhf(u4.y) * z1 + x4.y * (1.0f - z1);
            float h2 = tanhf(u4.z) * z2 + x4.z * (1.0f - z2);
            float h3 = tanhf(u4.w) * z3 + x4.w * (1.0f - z3);
            *reinterpret_cast<float4*>(out + o) = make_float4(h0, h1, h2, h3);
        }
    }
}

/* ================= launch ================= */
extern "C" void kernel_launch(void* const* d_in, const int* in_sizes, int n_in,
                              void* d_out, int out_size) {
    const float* x      = (const float*)d_in[0];
    const void*  ei     = d_in[1];
    const void*  et     = d_in[2];
    const float* weight = (const float*)d_in[3];
    const float* root   = (const float*)d_in[4];
    const float* bias   = (const float*)d_in[5];
    const float* w_gate = (const float*)d_in[6];
    const float* b_gate = (const float*)d_in[7];
    float*       out    = (float*)d_out;

    cudaFuncSetAttribute(gemm_wmma<0>, cudaFuncAttributeMaxDynamicSharedMemorySize, SMEM_BYTES);
    cudaFuncSetAttribute(gemm_wmma<1>, cudaFuncAttributeMaxDynamicSharedMemorySize, SMEM_BYTES);

    detect_kernel<<<1, 32>>>((const int*)ei);
    zero_scratch_kernel<<<1024, 256>>>();
    scatter_kernel<<<NEDGE, 256>>>(x, ei, et);

    dim3 grid(DIM / BN, (N_NODES + BM - 1) / BM);   /* 4 x 79 */
    gemm_wmma<0><<<grid, NTHREADS, SMEM_BYTES>>>(x, root, weight, bias, nullptr);
    gemm_wmma<1><<<grid, NTHREADS, SMEM_BYTES>>>(x, w_gate, nullptr, b_gate, out);
}

// round 15
// speedup vs baseline: 1.7597x; 1.1383x over previous
#include <cuda_runtime.h>
#include <mma.h>
#include <math.h>
#include <stdint.h>

using namespace nvcuda;

#define N_NODES 10000
#define DIM     1024
#define NREL    8
#define NEDGE   80000
#define K1      9216
#define K2      2048

#define BM 64
#define BN 128
#define BK 64
#define NTHREADS 256
#define ALD 68                          /* A smem row stride (floats) */
#define BLD 132                         /* B smem row stride (floats) */
#define CLD 132                         /* epilogue staging stride    */
#define A_TILE_FLOATS (BM * ALD)        /* 4352  */
#define B_TILE_FLOATS (BK * BLD)        /* 8448  */
#define STAGE_FLOATS  (A_TILE_FLOATS + B_TILE_FLOATS)   /* 12800 */
#define SMEM_BYTES    (STAGE_FLOATS * 4)                /* 51200 (>= 64*CLD*4 = 33792) */

/* Scratch device globals — PROVEN set only. */
__device__ float g_agg[(size_t)N_NODES * NREL * DIM];
__device__ float g_cnt[N_NODES * NREL];
__device__ float g_U[(size_t)N_NODES * DIM];
__device__ int   g_is64;

__device__ __forceinline__ float f2tf32(float f) {
    uint32_t r;
    asm("cvt.rna.tf32.f32 %0, %1;" : "=r"(r) : "f"(f));
    return __uint_as_float(r);
}

/* ================= prep kernels (verbatim, proven) ================= */
__global__ void detect_kernel(const int* __restrict__ ei) {
    if (threadIdx.x == 0 && blockIdx.x == 0) {
        int allzero = 1;
        for (int i = 1; i < 4096; i += 2)
            if (ei[i] != 0) { allzero = 0; break; }
        g_is64 = allzero;
    }
}

__global__ void zero_scratch_kernel() {
    size_t idx    = (size_t)blockIdx.x * blockDim.x + threadIdx.x;
    size_t stride = (size_t)gridDim.x * blockDim.x;
    float4* agg4 = reinterpret_cast<float4*>(g_agg);
    const size_t nagg4 = (size_t)N_NODES * NREL * DIM / 4;
    for (size_t i = idx; i < nagg4; i += stride)
        agg4[i] = make_float4(0.f, 0.f, 0.f, 0.f);
    float4* cnt4 = reinterpret_cast<float4*>(g_cnt);
    const size_t ncnt4 = (size_t)N_NODES * NREL / 4;
    for (size_t i = idx; i < ncnt4; i += stride)
        cnt4[i] = make_float4(0.f, 0.f, 0.f, 0.f);
}

__global__ __launch_bounds__(256)
void scatter_kernel(const float* __restrict__ x,
                    const void* __restrict__ edge_index,
                    const void* __restrict__ edge_type) {
    int e = blockIdx.x;
    int src, dst, r;
    if (g_is64) {
        const long long* ei = (const long long*)edge_index;
        const long long* et = (const long long*)edge_type;
        src = (int)ei[e]; dst = (int)ei[NEDGE + e]; r = (int)et[e];
    } else {
        const int* ei = (const int*)edge_index;
        const int* et = (const int*)edge_type;
        src = ei[e]; dst = ei[NEDGE + e]; r = et[e];
    }
    const float4* xs = reinterpret_cast<const float4*>(x + (size_t)src * DIM);
    float* out = g_agg + ((size_t)dst * NREL + r) * DIM;
    int t = threadIdx.x;
    float4 v = xs[t];
    atomicAdd(out + t * 4 + 0, v.x);
    atomicAdd(out + t * 4 + 1, v.y);
    atomicAdd(out + t * 4 + 2, v.z);
    atomicAdd(out + t * 4 + 3, v.w);
    if (t == 0)
        atomicAdd(&g_cnt[dst * NREL + r], 1.0f);
}

/* ================= WMMA tf32 GEMM, 3 CTAs/SM (24 warps) ============
   R9's proven bulk-synchronous structure; CTA tile 64x128, warp tile
   32x32 (acc = 32 regs) so 3 CTAs x 256 thr fit the 64K register file
   with zero spills. Rounding + mean-normalization fused at STS.
   MODE 0: U = [x | mean] @ [root ; weight] + bias     (K = 9216)
   MODE 1: z = [u | x] @ w_gate + b_gate; fused gate   (K = 2048)      */
template <int MODE>
__global__ __launch_bounds__(NTHREADS, 3)
void gemm_wmma(const float* __restrict__ x,
               const float* __restrict__ B0,      /* root   | w_gate  */
               const float* __restrict__ B1,      /* weight | unused  */
               const float* __restrict__ bvec,
               float* __restrict__ out) {
    extern __shared__ float smem[];
    const int tid = threadIdx.x;
    const int wid = tid >> 5;
    const int m0  = blockIdx.y * BM;
    const int n0  = blockIdx.x * BN;
    const int KDIM = MODE ? K2 : K1;
    const int NC   = KDIM / BK;

    float* Abuf = smem;
    float* Bbuf = smem + A_TILE_FLOATS;

    const int wm = (wid & 1) * 32;     /* warp rows: 2 x 16 */
    const int wn = (wid >> 1) * 32;    /* warp cols: 2 x 16 */

    wmma::fragment<wmma::accumulator, 16, 16, 8, float> acc[2][2];
#pragma unroll
    for (int mt = 0; mt < 2; mt++)
#pragma unroll
        for (int nt = 0; nt < 2; nt++)
            wmma::fill_fragment(acc[mt][nt], 0.0f);

    for (int ci = 0; ci < NC; ci++) {
        const int k0 = ci * BK;
        __syncthreads();               /* prev readers done before overwrite */

        /* ---- load phase: A 64x64, B 64x128, tf32-round at STS ---- */
#pragma unroll
        for (int t = 0; t < 4; t++) {
            int idx = tid + t * NTHREADS;
            int row = idx >> 4;                  /* 16 float4 per A row */
            int c4  = (idx & 15) << 2;
            int grow = m0 + row;
            float4 v = make_float4(0.f, 0.f, 0.f, 0.f);
            if (grow < N_NODES) {
                int k = k0 + c4;
                if (MODE == 0) {
                    if (k < DIM) {
                        v = *reinterpret_cast<const float4*>(x + (size_t)grow * DIM + k);
                    } else {
                        int kk = k - DIM;
                        int r  = kk >> 10;
                        float s = 1.0f / fmaxf(g_cnt[grow * NREL + r], 1.0f);
                        float4 a = *reinterpret_cast<const float4*>(
                            g_agg + (size_t)grow * (NREL * DIM) + kk);
                        v.x = a.x * s; v.y = a.y * s; v.z = a.z * s; v.w = a.w * s;
                    }
                } else {
                    const float* Ap = (k < DIM)
                        ? (g_U + (size_t)grow * DIM + k)
                        : (x + (size_t)grow * DIM + (k - DIM));
                    v = *reinterpret_cast<const float4*>(Ap);
                }
            }
            float* p = Abuf + row * ALD + c4;
            p[0] = f2tf32(v.x); p[1] = f2tf32(v.y);
            p[2] = f2tf32(v.z); p[3] = f2tf32(v.w);
        }
#pragma unroll
        for (int t = 0; t < 8; t++) {
            int idx = tid + t * NTHREADS;
            int kr  = idx >> 5;                  /* 0..63 */
            int c4  = (idx & 31) << 2;
            int k   = k0 + kr;
            const float* src;
            if (MODE == 0)
                src = (k < DIM) ? (B0 + (size_t)k * DIM + n0 + c4)
                                : (B1 + (size_t)(k - DIM) * DIM + n0 + c4);
            else
                src = B0 + (size_t)k * DIM + n0 + c4;
            float4 v = *reinterpret_cast<const float4*>(src);
            float* p = Bbuf + kr * BLD + c4;
            p[0] = f2tf32(v.x); p[1] = f2tf32(v.y);
            p[2] = f2tf32(v.z); p[3] = f2tf32(v.w);
        }
        __syncthreads();

        /* ---- MMA phase ---- */
#pragma unroll
        for (int kk = 0; kk < 8; kk++) {
            wmma::fragment<wmma::matrix_b, 16, 16, 8,
                           wmma::precision::tf32, wmma::row_major> fb[2];
#pragma unroll
            for (int nt = 0; nt < 2; nt++)
                wmma::load_matrix_sync(fb[nt], Bbuf + (kk * 8) * BLD + wn + nt * 16, BLD);
#pragma unroll
            for (int mt = 0; mt < 2; mt++) {
                wmma::fragment<wmma::matrix_a, 16, 16, 8,
                               wmma::precision::tf32, wmma::row_major> fa;
                wmma::load_matrix_sync(fa, Abuf + (wm + mt * 16) * ALD + kk * 8, ALD);
#pragma unroll
                for (int nt = 0; nt < 2; nt++)
                    wmma::mma_sync(acc[mt][nt], fa, fb[nt], acc[mt][nt]);
            }
        }
    }

    /* ---- epilogue: stage accumulators in smem, then elementwise ---- */
    __syncthreads();
    float* stg = smem;                       /* 64 x CLD fits in SMEM_BYTES */
#pragma unroll
    for (int mt = 0; mt < 2; mt++)
#pragma unroll
        for (int nt = 0; nt < 2; nt++)
            wmma::store_matrix_sync(stg + (wm + mt * 16) * CLD + wn + nt * 16,
                                    acc[mt][nt], CLD, wmma::mem_row_major);
    __syncthreads();

#pragma unroll
    for (int t = 0; t < 8; t++) {
        int idx = tid + t * NTHREADS;        /* 2048 float4 = 64x128 */
        int row = idx >> 5;
        int c4  = (idx & 31) << 2;
        int grow = m0 + row;
        if (grow >= N_NODES) continue;
        int gc = n0 + c4;
        const float* sp = stg + row * CLD + c4;
        float4 bv = *reinterpret_cast<const float4*>(bvec + gc);
        float z0 = sp[0] + bv.x, z1 = sp[1] + bv.y;
        float z2 = sp[2] + bv.z, z3 = sp[3] + bv.w;
        size_t o = (size_t)grow * DIM + gc;
        if (MODE == 0) {
            *reinterpret_cast<float4*>(g_U + o) = make_float4(z0, z1, z2, z3);
        } else {
            float4 u4 = *reinterpret_cast<const float4*>(g_U + o);
            float4 x4 = *reinterpret_cast<const float4*>(x + o);
            float h0 = tanhf(u4.x) * z0 + x4.x * (1.0f - z0);
            float h1 = tanhf(u4.y) * z1 + x4.y * (1.0f - z1);
            float h2 = tanhf(u4.z) * z2 + x4.z * (1.0f - z2);
            float h3 = tanhf(u4.w) * z3 + x4.w * (1.0f - z3);
            *reinterpret_cast<float4*>(out + o) = make_float4(h0, h1, h2, h3);
        }
    }
}

/* ================= launch ================= */
extern "C" void kernel_launch(void* const* d_in, const int* in_sizes, int n_in,
                              void* d_out, int out_size) {
    const float* x      = (const float*)d_in[0];
    const void*  ei     = d_in[1];
    const void*  et     = d_in[2];
    const float* weight = (const float*)d_in[3];
    const float* root   = (const float*)d_in[4];
    const float* bias   = (const float*)d_in[5];
    const float* w_gate = (const float*)d_in[6];
    const float* b_gate = (const float*)d_in[7];
    float*       out    = (float*)d_out;

    cudaFuncSetAttribute(gemm_wmma<0>, cudaFuncAttributeMaxDynamicSharedMemorySize, SMEM_BYTES);
    cudaFuncSetAttribute(gemm_wmma<1>, cudaFuncAttributeMaxDynamicSharedMemorySize, SMEM_BYTES);

    detect_kernel<<<1, 32>>>((const int*)ei);
    zero_scratch_kernel<<<1024, 256>>>();
    scatter_kernel<<<NEDGE, 256>>>(x, ei, et);

    dim3 grid(DIM / BN, (N_NODES + BM - 1) / BM);   /* 8 x 157 */
    gemm_wmma<0><<<grid, NTHREADS, SMEM_BYTES>>>(x, root, weight, bias, nullptr);
    gemm_wmma<1><<<grid, NTHREADS, SMEM_BYTES>>>(x, w_gate, nullptr, b_gate, out);
}

// round 16
// speedup vs baseline: 2.2752x; 1.2930x over previous
#include <cuda_runtime.h>
#include <mma.h>
#include <math.h>
#include <stdint.h>

using namespace nvcuda;

#define N_NODES 10000
#define DIM     1024
#define NREL    8
#define NEDGE   80000
#define K1      9216
#define K2      2048

#define BM 128
#define BN 128
#define BK 64
#define NTHREADS 256
#define ALD 72                          /* A smem row stride (8-bank offset) */
#define BLD 136                         /* B smem row stride (8-bank offset) */
#define CLD 136                         /* epilogue staging stride           */
#define A_TILE_FLOATS (BM * ALD)        /* 9216  */
#define B_TILE_FLOATS (BK * BLD)        /* 8704  */
#define STAGE_FLOATS  (A_TILE_FLOATS + B_TILE_FLOATS)  /* 17920 */
#define SMEM_BYTES    (STAGE_FLOATS * 4)               /* 71680 (>= 128*CLD*4 = 69632) */

/* Scratch device globals — PROVEN set only. */
__device__ float g_agg[(size_t)N_NODES * NREL * DIM];
__device__ float g_cnt[N_NODES * NREL];
__device__ float g_U[(size_t)N_NODES * DIM];
__device__ int   g_is64;

__device__ __forceinline__ float f2tf32(float f) {
    uint32_t r;
    asm("cvt.rna.tf32.f32 %0, %1;" : "=r"(r) : "f"(f));
    return __uint_as_float(r);
}

/* ================= prep kernels ================= */
__global__ void detect_kernel(const int* __restrict__ ei) {
    if (threadIdx.x == 0 && blockIdx.x == 0) {
        int allzero = 1;
        for (int i = 1; i < 4096; i += 2)
            if (ei[i] != 0) { allzero = 0; break; }
        g_is64 = allzero;
    }
}

__global__ void zero_scratch_kernel() {
    size_t idx    = (size_t)blockIdx.x * blockDim.x + threadIdx.x;
    size_t stride = (size_t)gridDim.x * blockDim.x;
    float4* agg4 = reinterpret_cast<float4*>(g_agg);
    const size_t nagg4 = (size_t)N_NODES * NREL * DIM / 4;
    for (size_t i = idx; i < nagg4; i += stride)
        agg4[i] = make_float4(0.f, 0.f, 0.f, 0.f);
    float4* cnt4 = reinterpret_cast<float4*>(g_cnt);
    const size_t ncnt4 = (size_t)N_NODES * NREL / 4;
    for (size_t i = idx; i < ncnt4; i += stride)
        cnt4[i] = make_float4(0.f, 0.f, 0.f, 0.f);
}

__global__ __launch_bounds__(256)
void scatter_kernel(const float* __restrict__ x,
                    const void* __restrict__ edge_index,
                    const void* __restrict__ edge_type) {
    int e = blockIdx.x;
    int src, dst, r;
    if (g_is64) {
        const long long* ei = (const long long*)edge_index;
        const long long* et = (const long long*)edge_type;
        src = (int)ei[e]; dst = (int)ei[NEDGE + e]; r = (int)et[e];
    } else {
        const int* ei = (const int*)edge_index;
        const int* et = (const int*)edge_type;
        src = ei[e]; dst = ei[NEDGE + e]; r = et[e];
    }
    const float4* xs = reinterpret_cast<const float4*>(x + (size_t)src * DIM);
    float* out = g_agg + ((size_t)dst * NREL + r) * DIM;
    int t = threadIdx.x;
    float4 v = xs[t];
    atomicAdd(out + t * 4 + 0, v.x);
    atomicAdd(out + t * 4 + 1, v.y);
    atomicAdd(out + t * 4 + 2, v.z);
    atomicAdd(out + t * 4 + 3, v.w);
    if (t == 0)
        atomicAdd(&g_cnt[dst * NREL + r], 1.0f);
}

/* g_agg row (node,rel): raw sums -> tf32-rounded mean, IN PLACE.
   After this pass the GEMM's agg loads are pure copies.            */
__global__ __launch_bounds__(256)
void normalize_kernel() {
    int row = blockIdx.x;                       /* 0 .. N_NODES*NREL-1 */
    float s = 1.0f / fmaxf(g_cnt[row], 1.0f);
    float4* p = reinterpret_cast<float4*>(g_agg) + (size_t)row * 256 + threadIdx.x;
    float4 v = *p;
    *p = make_float4(f2tf32(v.x * s), f2tf32(v.y * s), f2tf32(v.z * s), f2tf32(v.w * s));
}

/* ================= WMMA tf32 GEMM (R9 structure + lean loads) ======
   Bulk-synchronous, 2 CTAs/SM, warp tile 32x64 (acc = 64 regs).
   A's agg region (pre-normalized, pre-rounded) loads as a pure copy;
   x / u regions round at STS. B rounds at STS.
   MODE 0: U = [x | mean] @ [root ; weight] + bias     (K = 9216)
   MODE 1: z = [u | x] @ w_gate + b_gate; fused gate   (K = 2048)      */
template <int MODE>
__global__ __launch_bounds__(NTHREADS, 2)
void gemm_wmma(const float* __restrict__ x,
               const float* __restrict__ B0,      /* root   | w_gate  */
               const float* __restrict__ B1,      /* weight | unused  */
               const float* __restrict__ bvec,
               float* __restrict__ out) {
    extern __shared__ float smem[];
    const int tid = threadIdx.x;
    const int wid = tid >> 5;
    const int m0  = blockIdx.y * BM;
    const int n0  = blockIdx.x * BN;
    const int KDIM = MODE ? K2 : K1;
    const int NC   = KDIM / BK;

    float* Abuf = smem;
    float* Bbuf = smem + A_TILE_FLOATS;

    const int wm = (wid & 3) * 32;     /* warp rows: 2 x 16 */
    const int wn = (wid >> 2) * 64;    /* warp cols: 4 x 16 */

    wmma::fragment<wmma::accumulator, 16, 16, 8, float> acc[2][4];
#pragma unroll
    for (int mt = 0; mt < 2; mt++)
#pragma unroll
        for (int nt = 0; nt < 4; nt++)
            wmma::fill_fragment(acc[mt][nt], 0.0f);

    for (int ci = 0; ci < NC; ci++) {
        const int k0 = ci * BK;
        __syncthreads();               /* prev readers done before overwrite */

        /* ---- load phase: A 128x64, B 64x128 ---- */
        if (MODE == 0 && k0 >= DIM) {
            /* agg region: pre-normalized + pre-rounded -> pure copy */
            const int kk0 = k0 - DIM;
#pragma unroll
            for (int t = 0; t < 8; t++) {
                int idx = tid + t * NTHREADS;
                int row = idx >> 4;
                int c4  = (idx & 15) << 2;
                int grow = m0 + row;
                float4 v = make_float4(0.f, 0.f, 0.f, 0.f);
                if (grow < N_NODES)
                    v = *reinterpret_cast<const float4*>(
                        g_agg + (size_t)grow * (NREL * DIM) + kk0 + c4);
                *reinterpret_cast<float4*>(Abuf + row * ALD + c4) = v;
            }
        } else {
#pragma unroll
            for (int t = 0; t < 8; t++) {
                int idx = tid + t * NTHREADS;
                int row = idx >> 4;                  /* 16 float4 per A row */
                int c4  = (idx & 15) << 2;
                int grow = m0 + row;
                float4 v = make_float4(0.f, 0.f, 0.f, 0.f);
                if (grow < N_NODES) {
                    int k = k0 + c4;
                    const float* Ap;
                    if (MODE == 0)
                        Ap = x + (size_t)grow * DIM + k;           /* k < DIM here */
                    else
                        Ap = (k < DIM) ? (g_U + (size_t)grow * DIM + k)
                                       : (x + (size_t)grow * DIM + (k - DIM));
                    v = *reinterpret_cast<const float4*>(Ap);
                }
                float* p = Abuf + row * ALD + c4;
                p[0] = f2tf32(v.x); p[1] = f2tf32(v.y);
                p[2] = f2tf32(v.z); p[3] = f2tf32(v.w);
            }
        }
#pragma unroll
        for (int t = 0; t < 8; t++) {
            int idx = tid + t * NTHREADS;
            int kr  = idx >> 5;                  /* 0..63 */
            int c4  = (idx & 31) << 2;
            int k   = k0 + kr;
            const float* src;
            if (MODE == 0)
                src = (k < DIM) ? (B0 + (size_t)k * DIM + n0 + c4)
                                : (B1 + (size_t)(k - DIM) * DIM + n0 + c4);
            else
                src = B0 + (size_t)k * DIM + n0 + c4;
            float4 v = *reinterpret_cast<const float4*>(src);
            float* p = Bbuf + kr * BLD + c4;
            p[0] = f2tf32(v.x); p[1] = f2tf32(v.y);
            p[2] = f2tf32(v.z); p[3] = f2tf32(v.w);
        }
        __syncthreads();

        /* ---- MMA phase ---- */
#pragma unroll
        for (int kk = 0; kk < 8; kk++) {
            wmma::fragment<wmma::matrix_b, 16, 16, 8,
                           wmma::precision::tf32, wmma::row_major> fb[4];
#pragma unroll
            for (int nt = 0; nt < 4; nt++)
                wmma::load_matrix_sync(fb[nt], Bbuf + (kk * 8) * BLD + wn + nt * 16, BLD);
#pragma unroll
            for (int mt = 0; mt < 2; mt++) {
                wmma::fragment<wmma::matrix_a, 16, 16, 8,
                               wmma::precision::tf32, wmma::row_major> fa;
                wmma::load_matrix_sync(fa, Abuf + (wm + mt * 16) * ALD + kk * 8, ALD);
#pragma unroll
                for (int nt = 0; nt < 4; nt++)
                    wmma::mma_sync(acc[mt][nt], fa, fb[nt], acc[mt][nt]);
            }
        }
    }

    /* ---- epilogue: stage accumulators in smem, then elementwise ---- */
    __syncthreads();
    float* stg = smem;                       /* 128 x CLD fits in SMEM_BYTES */
#pragma unroll
    for (int mt = 0; mt < 2; mt++)
#pragma unroll
        for (int nt = 0; nt < 4; nt++)
            wmma::store_matrix_sync(stg + (wm + mt * 16) * CLD + wn + nt * 16,
                                    acc[mt][nt], CLD, wmma::mem_row_major);
    __syncthreads();

#pragma unroll
    for (int t = 0; t < 16; t++) {
        int idx = tid + t * NTHREADS;        /* 4096 float4 = 128x128 */
        int row = idx >> 5;
        int c4  = (idx & 31) << 2;
        int grow = m0 + row;
        if (grow >= N_NODES) continue;
        int gc = n0 + c4;
        const float* sp = stg + row * CLD + c4;
        float4 bv = *reinterpret_cast<const float4*>(bvec + gc);
        float z0 = sp[0] + bv.x, z1 = sp[1] + bv.y;
        float z2 = sp[2] + bv.z, z3 = sp[3] + bv.w;
        size_t o = (size_t)grow * DIM + gc;
        if (MODE == 0) {
            *reinterpret_cast<float4*>(g_U + o) = make_float4(z0, z1, z2, z3);
        } else {
            float4 u4 = *reinterpret_cast<const float4*>(g_U + o);
            float4 x4 = *reinterpret_cast<const float4*>(x + o);
            float h0 = tanhf(u4.x) * z0 + x4.x * (1.0f - z0);
            float h1 = tanhf(u4.y) * z1 + x4.y * (1.0f - z1);
            float h2 = tanhf(u4.z) * z2 + x4.z * (1.0f - z2);
            float h3 = tanhf(u4.w) * z3 + x4.w * (1.0f - z3);
            *reinterpret_cast<float4*>(out + o) = make_float4(h0, h1, h2, h3);
        }
    }
}

/* ================= launch ================= */
extern "C" void kernel_launch(void* const* d_in, const int* in_sizes, int n_in,
                              void* d_out, int out_size) {
    const float* x      = (const float*)d_in[0];
    const void*  ei     = d_in[1];
    const void*  et     = d_in[2];
    const float* weight = (const float*)d_in[3];
    const float* root   = (const float*)d_in[4];
    const float* bias   = (const float*)d_in[5];
    const float* w_gate = (const float*)d_in[6];
    const float* b_gate = (const float*)d_in[7];
    float*       out    = (float*)d_out;

    cudaFuncSetAttribute(gemm_wmma<0>, cudaFuncAttributeMaxDynamicSharedMemorySize, SMEM_BYTES);
    cudaFuncSetAttribute(gemm_wmma<1>, cudaFuncAttributeMaxDynamicSharedMemorySize, SMEM_BYTES);

    detect_kernel<<<1, 32>>>((const int*)ei);
    zero_scratch_kernel<<<1024, 256>>>();
    scatter_kernel<<<NEDGE, 256>>>(x, ei, et);
    normalize_kernel<<<N_NODES * NREL, 256>>>();

    dim3 grid(DIM / BN, (N_NODES + BM - 1) / BM);   /* 8 x 79 */
    gemm_wmma<0><<<grid, NTHREADS, SMEM_BYTES>>>(x, root, weight, bias, nullptr);
    gemm_wmma<1><<<grid, NTHREADS, SMEM_BYTES>>>(x, w_gate, nullptr, b_gate, out);
}